// round 14
// baseline (speedup 1.0000x reference)
#include <cuda_runtime.h>
#include <math.h>

// Problem constants
#define BB 32
#define TT 4096
#define NN 11
#define FF 16
#define HH 32
#define TPB 32                 // t-values per block
#define THREADS 176            // (TPB/2) * NN ; each thread does 2 t-rows
#define ROW 176                // NN*FF floats per (b,t)

typedef unsigned long long u64;

// ---- packed f32x2 helpers (sm_100+) ----
__device__ __forceinline__ u64 fma2(u64 a, u64 b, u64 c) {
    u64 d;
    asm("fma.rn.f32x2 %0, %1, %2, %3;" : "=l"(d) : "l"(a), "l"(b), "l"(c));
    return d;
}
__device__ __forceinline__ u64 add2(u64 a, u64 b) {
    u64 d;
    asm("add.rn.f32x2 %0, %1, %2;" : "=l"(d) : "l"(a), "l"(b));
    return d;
}
__device__ __forceinline__ u64 mul2(u64 a, u64 b) {
    u64 d;
    asm("mul.rn.f32x2 %0, %1, %2;" : "=l"(d) : "l"(a), "l"(b));
    return d;
}
__device__ __forceinline__ u64 dup2(float v) {
    u64 r;
    asm("mov.b64 %0, {%1, %1};" : "=l"(r) : "f"(v));
    return r;
}
__device__ __forceinline__ u64 pk2(float lo, float hi) {
    u64 r;
    asm("mov.b64 %0, {%1, %2};" : "=l"(r) : "f"(lo), "f"(hi));
    return r;
}
__device__ __forceinline__ float2 upk2(u64 v) {
    float2 f;
    asm("mov.b64 {%0, %1}, %2;" : "=f"(f.x), "=f"(f.y) : "l"(v));
    return f;
}
__device__ __forceinline__ float rcpf(float x) {
    float r;
    asm("rcp.approx.f32 %0, %1;" : "=f"(r) : "f"(x));
    return r;
}
__device__ __forceinline__ float ex2f(float x) {
    float r;
    asm("ex2.approx.f32 %0, %1;" : "=f"(r) : "f"(x));
    return r;
}

// ---- packed GELU on pre-scaled input U = v/sqrt(2) (pair) ----
// gelu(v) = c*u*(1+erf(u)), c = 1/sqrt(2); erf via A&S 7.1.26 (|err|<=1.5e-7).
// Sign trick: erf(u) = sign(u)*r with r>=0  =>  u*erf(u) = |u|*r,
// so gelu = c*u + c*|u|*r  — no copysign / final unpack needed.
__device__ __forceinline__ u64 gelu2p(u64 U) {
    const u64 ABS2 = 0x7FFFFFFF7FFFFFFFULL;
    const u64 ONE2 = 0x3F8000003F800000ULL;
    u64 au = U & ABS2;                                   // |u| (2x LOP)
    // t = 1/(1 + 0.3275911*|u|)
    u64 d = fma2(dup2(0.3275911f), au, ONE2);
    float2 df = upk2(d);
    u64 t = pk2(rcpf(df.x), rcpf(df.y));
    // Horner with negated A&S coeffs: p = -q(t)
    u64 p = fma2(dup2(-1.061405429f), t, dup2(1.453152027f));
    p = fma2(p, t, dup2(-1.421413741f));
    p = fma2(p, t, dup2(0.284496736f));
    p = fma2(p, t, dup2(-0.254829592f));
    p = mul2(p, t);
    // e = exp(-u^2) = 2^(-log2e * u^2)
    u64 u2 = mul2(U, U);
    u64 w  = mul2(dup2(-1.4426950408889634f), u2);
    float2 wf = upk2(w);
    u64 e = pk2(ex2f(wf.x), ex2f(wf.y));
    // r = 1 - q*e = fma(p, e, 1)   in [0,1]
    u64 r = fma2(p, e, ONE2);
    // gelu = c*u + (c*|u|)*r
    u64 h  = mul2(dup2(0.70710678118654752f), U);
    u64 h2 = mul2(dup2(0.70710678118654752f), au);
    return fma2(h2, r, h);
}

__global__ __launch_bounds__(THREADS, 3)
void fused_proj_mlp_kernel(
    const float* __restrict__ x,          // [B,T,N,F]
    const int*   __restrict__ lab_idx,    // [B]
    const float* __restrict__ projection, // [LABS,N,N]
    const float* __restrict__ bias,       // [LABS,1,N,F]
    const float* __restrict__ w1,         // [F,H]
    const float* __restrict__ b1,         // [H]
    const float* __restrict__ ln_g,       // [H]
    const float* __restrict__ ln_b,       // [H]
    const float* __restrict__ w2,         // [H,F]
    const float* __restrict__ b2,         // [F]
    float* __restrict__ out)              // [B,T,N,F]
{
    __shared__ __align__(16) float xs[TPB * ROW];     // flat x tile
    __shared__ __align__(16) float Ws[NN * NN];
    __shared__ __align__(16) float bias_s[NN * FF];
    __shared__ __align__(16) float w1s[FF * HH];
    __shared__ __align__(16) float w2s[HH * FF];
    __shared__ __align__(16) float b1s[HH];
    __shared__ __align__(16) float gs[HH];
    __shared__ __align__(16) float bls[HH];            // pre-scaled by 1/sqrt(2)
    __shared__ __align__(16) float b2s[FF];

    const int tid = threadIdx.x;
    const int b   = blockIdx.y;
    const int t0  = blockIdx.x * TPB;
    const int lab = lab_idx[b];

    // ---- stage x tile (1408 float4, 8 per thread) ----
    {
        const float4* xg = (const float4*)(x + ((size_t)(b * TT + t0)) * ROW);
        float4* xd = (float4*)xs;
        #pragma unroll
        for (int i = 0; i < 8; i++) {
            int idx = tid + i * THREADS;
            xd[idx] = xg[idx];
        }
    }
    // ---- stage params ----
    if (tid < NN * NN)   Ws[tid]     = projection[lab * NN * NN + tid];
    if (tid < NN * FF)   bias_s[tid] = bias[lab * NN * FF + tid];
    #pragma unroll
    for (int i = tid; i < FF * HH; i += THREADS) { w1s[i] = w1[i]; w2s[i] = w2[i]; }
    if (tid < HH) {
        b1s[tid] = b1[tid];
        gs[tid]  = ln_g[tid];
        bls[tid] = ln_b[tid] * 0.70710678118654752f;   // fold 1/sqrt(2) into LN bias
    }
    if (tid < FF) b2s[tid] = b2[tid];
    __syncthreads();

    const int m  = tid % NN;       // output channel (same for both rows)
    const int tl = tid / NN;       // 0..15 ; rows tl and tl+16

    // ---- projection: acc[f] = bias[m,f] + sum_n x[t,n,f] * W[n,m] ----
    u64 wnp[NN];
    #pragma unroll
    for (int n = 0; n < NN; n++) wnp[n] = dup2(Ws[n * NN + m]);

    u64 aA[8], aB[8];
    {
        const ulonglong2* bv = (const ulonglong2*)(bias_s + m * FF);
        #pragma unroll
        for (int q = 0; q < 4; q++) {
            ulonglong2 v = bv[q];
            aA[2*q] = v.x; aA[2*q+1] = v.y;
            aB[2*q] = v.x; aB[2*q+1] = v.y;
        }
    }
    {
        const ulonglong2* xA = (const ulonglong2*)(xs + tl * ROW);
        const ulonglong2* xB = (const ulonglong2*)(xs + (tl + 16) * ROW);
        #pragma unroll
        for (int n = 0; n < NN; n++) {
            u64 w = wnp[n];
            #pragma unroll
            for (int q = 0; q < 4; q++) {
                ulonglong2 va = xA[n * 4 + q];
                ulonglong2 vb = xB[n * 4 + q];
                aA[2*q]   = fma2(va.x, w, aA[2*q]);
                aA[2*q+1] = fma2(va.y, w, aA[2*q+1]);
                aB[2*q]   = fma2(vb.x, w, aB[2*q]);
                aB[2*q+1] = fma2(vb.y, w, aB[2*q+1]);
            }
        }
    }

    // ---- MLP1: h[j] = b1[j] + sum_f ov[f] * w1[f,j] (weights shared by both rows) ----
    u64 hA[16], hB[16];
    {
        const ulonglong2* bv = (const ulonglong2*)b1s;
        #pragma unroll
        for (int q = 0; q < 8; q++) {
            ulonglong2 v = bv[q];
            hA[2*q] = v.x; hA[2*q+1] = v.y;
            hB[2*q] = v.x; hB[2*q+1] = v.y;
        }
    }
    #pragma unroll
    for (int p = 0; p < 8; p++) {                 // f = 2p, 2p+1
        float2 ua = upk2(aA[p]);
        float2 ub = upk2(aB[p]);
        #pragma unroll
        for (int s = 0; s < 2; s++) {
            int f = 2 * p + s;
            u64 ba = dup2(s == 0 ? ua.x : ua.y);
            u64 bb = dup2(s == 0 ? ub.x : ub.y);
            const ulonglong2* wr = (const ulonglong2*)(w1s + f * HH);
            #pragma unroll
            for (int q = 0; q < 8; q++) {
                ulonglong2 wv = wr[q];
                hA[2*q]   = fma2(ba, wv.x, hA[2*q]);
                hA[2*q+1] = fma2(ba, wv.y, hA[2*q+1]);
                hB[2*q]   = fma2(bb, wv.x, hB[2*q]);
                hB[2*q+1] = fma2(bb, wv.y, hB[2*q+1]);
            }
        }
    }

    // ---- LayerNorm (fully packed) ----
    float muA, rA, muB, rB;
    {
        u64 SA = hA[0], SB = hB[0];
        u64 QA = mul2(hA[0], hA[0]), QB = mul2(hB[0], hB[0]);
        #pragma unroll
        for (int k = 1; k < 16; k++) {
            SA = add2(SA, hA[k]);       SB = add2(SB, hB[k]);
            QA = fma2(hA[k], hA[k], QA); QB = fma2(hB[k], hB[k], QB);
        }
        float2 sa = upk2(SA), sb = upk2(SB), qa = upk2(QA), qb = upk2(QB);
        float sAf = sa.x + sa.y, sBf = sb.x + sb.y;
        float qAf = qa.x + qa.y, qBf = qb.x + qb.y;
        muA = sAf * (1.f / HH);  muB = sBf * (1.f / HH);
        // rstd pre-scaled by 1/sqrt(2): LN+scale produces u = v/sqrt(2) directly
        rA = rsqrtf(qAf * (1.f / HH) - muA * muA + 1e-5f) * 0.70710678118654752f;
        rB = rsqrtf(qBf * (1.f / HH) - muB * muB + 1e-5f) * 0.70710678118654752f;
    }
    // normalize + affine (pre-scaled) + packed GELU; h := gelu(ln(h))
    {
        const u64 rA2 = dup2(rA), rB2 = dup2(rB);
        const u64 nmA = dup2(-muA), nmB = dup2(-muB);
        const ulonglong2* gv = (const ulonglong2*)gs;
        const ulonglong2* bv = (const ulonglong2*)bls;
        #pragma unroll
        for (int q = 0; q < 8; q++) {
            ulonglong2 gg = gv[q];
            ulonglong2 bb = bv[q];
            // c1 = rstd'*g ; c0 = -mu*c1 + b' ; u = h*c1 + c0  (u = v/sqrt(2))
            u64 c1A0 = mul2(rA2, gg.x), c1A1 = mul2(rA2, gg.y);
            u64 c1B0 = mul2(rB2, gg.x), c1B1 = mul2(rB2, gg.y);
            u64 c0A0 = fma2(nmA, c1A0, bb.x), c0A1 = fma2(nmA, c1A1, bb.y);
            u64 c0B0 = fma2(nmB, c1B0, bb.x), c0B1 = fma2(nmB, c1B1, bb.y);
            hA[2*q]   = gelu2p(fma2(hA[2*q],   c1A0, c0A0));
            hA[2*q+1] = gelu2p(fma2(hA[2*q+1], c1A1, c0A1));
            hB[2*q]   = gelu2p(fma2(hB[2*q],   c1B0, c0B0));
            hB[2*q+1] = gelu2p(fma2(hB[2*q+1], c1B1, c0B1));
        }
    }

    // ---- MLP2: y[f] = b2[f] + sum_j g[j] * w2[j,f] ----
    u64 yA[8], yB[8];
    {
        const ulonglong2* bv = (const ulonglong2*)b2s;
        #pragma unroll
        for (int q = 0; q < 4; q++) {
            ulonglong2 v = bv[q];
            yA[2*q] = v.x; yA[2*q+1] = v.y;
            yB[2*q] = v.x; yB[2*q+1] = v.y;
        }
    }
    #pragma unroll
    for (int p = 0; p < 16; p++) {               // j = 2p, 2p+1
        float2 ga = upk2(hA[p]);
        float2 gb = upk2(hB[p]);
        #pragma unroll
        for (int s = 0; s < 2; s++) {
            int j = 2 * p + s;
            u64 ba = dup2(s == 0 ? ga.x : ga.y);
            u64 bb = dup2(s == 0 ? gb.x : gb.y);
            const ulonglong2* wr = (const ulonglong2*)(w2s + j * FF);
            #pragma unroll
            for (int q = 0; q < 4; q++) {
                ulonglong2 wv = wr[q];
                yA[2*q]   = fma2(ba, wv.x, yA[2*q]);
                yA[2*q+1] = fma2(ba, wv.y, yA[2*q+1]);
                yB[2*q]   = fma2(bb, wv.x, yB[2*q]);
                yB[2*q+1] = fma2(bb, wv.y, yB[2*q+1]);
            }
        }
    }

    // ---- store both rows, float4 ----
    float* ygA = out + (((size_t)(b * TT + t0 + tl)) * NN + m) * FF;
    float* ygB = out + (((size_t)(b * TT + t0 + tl + 16)) * NN + m) * FF;
    #pragma unroll
    for (int k = 0; k < 4; k++) {
        float2 a0 = upk2(yA[2*k]); float2 a1 = upk2(yA[2*k+1]);
        float2 b0 = upk2(yB[2*k]); float2 b1v = upk2(yB[2*k+1]);
        *(float4*)(ygA + 4*k) = make_float4(a0.x, a0.y, a1.x, a1.y);
        *(float4*)(ygB + 4*k) = make_float4(b0.x, b0.y, b1v.x, b1v.y);
    }
}

extern "C" void kernel_launch(void* const* d_in, const int* in_sizes, int n_in,
                              void* d_out, int out_size) {
    const float* x          = (const float*)d_in[0];
    const int*   lab_idx    = (const int*)  d_in[1];
    const float* projection = (const float*)d_in[2];
    const float* bias       = (const float*)d_in[3];
    const float* w1         = (const float*)d_in[4];
    const float* b1         = (const float*)d_in[5];
    const float* ln_g       = (const float*)d_in[6];
    const float* ln_b       = (const float*)d_in[7];
    const float* w2         = (const float*)d_in[8];
    const float* b2         = (const float*)d_in[9];
    float* out = (float*)d_out;

    dim3 grid(TT / TPB, BB);   // (128, 32)
    fused_proj_mlp_kernel<<<grid, THREADS>>>(
        x, lab_idx, projection, bias, w1, b1, ln_g, ln_b, w2, b2, out);
}

// round 17
// speedup vs baseline: 1.2420x; 1.2420x over previous
#include <cuda_runtime.h>
#include <cuda_bf16.h>
#include <math.h>
#include <stdint.h>

// Problem constants
#define NN 11
#define FF 16
#define HH 32
#define THREADS 256
#define GRID_BLKS 5632           // 32*4096*11 / 256 ; 176 CTAs per batch sample

typedef unsigned long long u64;

// ---------------- packed f32x2 helpers ----------------
__device__ __forceinline__ u64 fma2(u64 a, u64 b, u64 c) {
    u64 d; asm("fma.rn.f32x2 %0, %1, %2, %3;" : "=l"(d) : "l"(a), "l"(b), "l"(c)); return d;
}
__device__ __forceinline__ u64 add2(u64 a, u64 b) {
    u64 d; asm("add.rn.f32x2 %0, %1, %2;" : "=l"(d) : "l"(a), "l"(b)); return d;
}
__device__ __forceinline__ u64 mul2(u64 a, u64 b) {
    u64 d; asm("mul.rn.f32x2 %0, %1, %2;" : "=l"(d) : "l"(a), "l"(b)); return d;
}
__device__ __forceinline__ u64 dup2(float v) {
    u64 r; asm("mov.b64 %0, {%1, %1};" : "=l"(r) : "f"(v)); return r;
}
__device__ __forceinline__ u64 pk2(float lo, float hi) {
    u64 r; asm("mov.b64 %0, {%1, %2};" : "=l"(r) : "f"(lo), "f"(hi)); return r;
}
__device__ __forceinline__ float2 upk2(u64 v) {
    float2 f; asm("mov.b64 {%0, %1}, %2;" : "=f"(f.x), "=f"(f.y) : "l"(v)); return f;
}
__device__ __forceinline__ float rcpf(float x) {
    float r; asm("rcp.approx.f32 %0, %1;" : "=f"(r) : "f"(x)); return r;
}
__device__ __forceinline__ float ex2f(float x) {
    float r; asm("ex2.approx.f32 %0, %1;" : "=f"(r) : "f"(x)); return r;
}
// pack two f32 -> bf16x2, element "lo" in low 16 bits
__device__ __forceinline__ uint32_t cvt_bf2(float lo, float hi) {
    uint32_t r; asm("cvt.rn.bf16x2.f32 %0, %1, %2;" : "=r"(r) : "f"(hi), "f"(lo)); return r;
}
// reconstruct packed f32 pair from bf16x2 (exact)
__device__ __forceinline__ u64 bf2_to_f32pair(uint32_t hp) {
    return pk2(__uint_as_float(hp << 16), __uint_as_float(hp & 0xFFFF0000u));
}

// ---------------- packed GELU on pre-scaled u = v/sqrt(2) (R13-proven) ----------------
__device__ __forceinline__ u64 gelu2p(u64 U) {
    const u64 ABS2 = 0x7FFFFFFF7FFFFFFFULL;
    const u64 ONE2 = 0x3F8000003F800000ULL;
    u64 au = U & ABS2;
    u64 d = fma2(dup2(0.3275911f), au, ONE2);
    float2 df = upk2(d);
    u64 t = pk2(rcpf(df.x), rcpf(df.y));
    u64 p = fma2(dup2(-1.061405429f), t, dup2(1.453152027f));
    p = fma2(p, t, dup2(-1.421413741f));
    p = fma2(p, t, dup2(0.284496736f));
    p = fma2(p, t, dup2(-0.254829592f));
    p = mul2(p, t);
    u64 u2 = mul2(U, U);
    u64 w  = mul2(dup2(-1.4426950408889634f), u2);
    float2 wf = upk2(w);
    u64 e = pk2(ex2f(wf.x), ex2f(wf.y));
    u64 r = fma2(p, e, ONE2);              // 1 - q*exp(-u^2) >= 0
    u64 h  = mul2(dup2(0.70710678118654752f), U);
    u64 h2 = mul2(dup2(0.70710678118654752f), au);
    return fma2(h2, r, h);                 // c*u + c*|u|*r
}

// ---------------- mma.sync m16n8k16 bf16 (generic PTX, sm_80+) ----------------
__device__ __forceinline__ void mma16816(float* c, const uint32_t* a, const uint32_t* b) {
    asm volatile("mma.sync.aligned.m16n8k16.row.col.f32.bf16.bf16.f32 "
        "{%0,%1,%2,%3}, {%4,%5,%6,%7}, {%8,%9}, {%0,%1,%2,%3};"
        : "+f"(c[0]), "+f"(c[1]), "+f"(c[2]), "+f"(c[3])
        : "r"(a[0]), "r"(a[1]), "r"(a[2]), "r"(a[3]), "r"(b[0]), "r"(b[1]));
}

// split a packed f32 pair into bf16x2 hi + bf16x2 lo
__device__ __forceinline__ void split_pair(u64 P, uint32_t& hv, uint32_t& lv) {
    float2 f = upk2(P);
    uint32_t hp = cvt_bf2(f.x, f.y);
    u64 lop = fma2(bf2_to_f32pair(hp), dup2(-1.f), P);
    float2 lf = upk2(lop);
    hv = hp;
    lv = cvt_bf2(lf.x, lf.y);
}

// A-staging: 256 rows x 20 words (hi pairs cols 0-7, lo pairs cols 8-15, pad 4)
// stride 20 words = 80B -> conflict-free fragment LDS pattern
#define ASTRIDE 20

__global__ __launch_bounds__(THREADS, 2)
void fused_mma_kernel(
    const float* __restrict__ x,          // [B,T,N,F]
    const int*   __restrict__ lab_idx,    // [B]
    const float* __restrict__ projection, // [LABS,N,N]
    const float* __restrict__ bias,       // [LABS,1,N,F]
    const float* __restrict__ w1,         // [F,H]
    const float* __restrict__ b1,         // [H]
    const float* __restrict__ ln_g,       // [H]
    const float* __restrict__ ln_b,       // [H]
    const float* __restrict__ w2,         // [H,F]
    const float* __restrict__ b2,         // [F]
    float* __restrict__ out)              // [B,T,N,F]
{
    __shared__ __align__(16) uint32_t astg[THREADS * ASTRIDE];
    __shared__ __align__(16) float Wp[NN * NN];
    __shared__ __align__(16) float bias_s[NN * FF];
    __shared__ __align__(16) float b1s[HH];
    __shared__ __align__(16) float gs[HH];
    __shared__ __align__(16) float bls[HH];
    __shared__ __align__(16) float b2s[FF];

    const int tid  = threadIdx.x;
    const int lane = tid & 31;
    const int wid  = tid >> 5;
    const int q    = lane & 3;
    const int grp  = lane >> 2;
    const int R0   = blockIdx.x * THREADS;

    // 176 CTAs per batch sample (45056 rows / 256), so lab is CTA-constant
    const int lab = lab_idx[blockIdx.x / 176];
    for (int i = tid; i < NN * NN; i += THREADS) Wp[i] = projection[lab * NN * NN + i];
    for (int i = tid; i < NN * FF; i += THREADS) bias_s[i] = bias[lab * NN * FF + i];
    if (tid < HH) {
        b1s[tid] = b1[tid];
        gs[tid]  = ln_g[tid];
        bls[tid] = ln_b[tid] * 0.70710678118654752f;   // fold 1/sqrt(2)
    }
    if (tid < FF) b2s[tid] = b2[tid];
    __syncthreads();

    // ================= projection (packed fp32): one full row per thread =================
    {
        const unsigned r = (unsigned)(R0 + tid);
        const unsigned bt = r / NN;
        const int m = (int)(r - bt * NN);
        u64 acc[8];
        const u64* bv = (const u64*)(bias_s + m * FF);
        #pragma unroll
        for (int i = 0; i < 8; i++) acc[i] = bv[i];
        const ulonglong2* xr = (const ulonglong2*)(x + (size_t)bt * (NN * FF));
        #pragma unroll
        for (int n = 0; n < NN; n++) {
            u64 w = dup2(Wp[n * NN + m]);
            ulonglong2 v0 = xr[n * 4 + 0];
            ulonglong2 v1 = xr[n * 4 + 1];
            ulonglong2 v2 = xr[n * 4 + 2];
            ulonglong2 v3 = xr[n * 4 + 3];
            acc[0] = fma2(v0.x, w, acc[0]);
            acc[1] = fma2(v0.y, w, acc[1]);
            acc[2] = fma2(v1.x, w, acc[2]);
            acc[3] = fma2(v1.y, w, acc[3]);
            acc[4] = fma2(v2.x, w, acc[4]);
            acc[5] = fma2(v2.y, w, acc[5]);
            acc[6] = fma2(v3.x, w, acc[6]);
            acc[7] = fma2(v3.y, w, acc[7]);
        }
        // split to bf16 hi/lo, stage to smem
        uint32_t hv[8], lv[8];
        #pragma unroll
        for (int i = 0; i < 8; i++) split_pair(acc[i], hv[i], lv[i]);
        uint32_t* arow = astg + tid * ASTRIDE;
        #pragma unroll
        for (int k = 0; k < 4; k++) {
            *(u64*)(arow + 2 * k)     = (u64)hv[2 * k] | ((u64)hv[2 * k + 1] << 32);
            *(u64*)(arow + 8 + 2 * k) = (u64)lv[2 * k] | ((u64)lv[2 * k + 1] << 32);
        }
    }
    __syncwarp();   // each warp reads only rows written by its own threads

    // ================= A1 fragments from staging =================
    const int rb = wid << 5;
    uint32_t A1h[2][4], A1l[2][4];
    #pragma unroll
    for (int mt = 0; mt < 2; mt++) {
        const uint32_t* s0 = astg + (rb + mt * 16 + grp) * ASTRIDE;
        const uint32_t* s1 = astg + (rb + mt * 16 + grp + 8) * ASTRIDE;
        A1h[mt][0] = s0[q];     A1h[mt][1] = s1[q];
        A1h[mt][2] = s0[q + 4]; A1h[mt][3] = s1[q + 4];
        A1l[mt][0] = s0[8 + q];     A1l[mt][1] = s1[8 + q];
        A1l[mt][2] = s0[12 + q];    A1l[mt][3] = s1[12 + q];
    }

    // ================= B1 fragments (w1: [F=16 K][H=32 N]) =================
    uint32_t B1h[4][2], B1l[4][2];
    {
        const int k0 = q * 2;
        #pragma unroll
        for (int nt = 0; nt < 4; nt++) {
            const int n = nt * 8 + grp;
            float wa = __ldg(&w1[(k0    ) * HH + n]);
            float wb = __ldg(&w1[(k0 + 1) * HH + n]);
            float wc = __ldg(&w1[(k0 + 8) * HH + n]);
            float wd = __ldg(&w1[(k0 + 9) * HH + n]);
            uint32_t h0, l0, h1, l1;
            split_pair(pk2(wa, wb), h0, l0);
            split_pair(pk2(wc, wd), h1, l1);
            B1h[nt][0] = h0; B1h[nt][1] = h1;
            B1l[nt][0] = l0; B1l[nt][1] = l1;
        }
    }

    // ================= MMA1: C1[2mt][4nt] = OV x w1 (3-term split) =================
    float C1[2][4][4];
    #pragma unroll
    for (int mt = 0; mt < 2; mt++)
        #pragma unroll
        for (int nt = 0; nt < 4; nt++) {
            #pragma unroll
            for (int i = 0; i < 4; i++) C1[mt][nt][i] = 0.f;
            mma16816(C1[mt][nt], A1h[mt], B1h[nt]);
            mma16816(C1[mt][nt], A1h[mt], B1l[nt]);
            mma16816(C1[mt][nt], A1l[mt], B1h[nt]);
        }

    // ================= +b1, LayerNorm stats (quad-shuffle reduce) =================
    float s[4] = {0, 0, 0, 0}, sq[4] = {0, 0, 0, 0};
    #pragma unroll
    for (int mt = 0; mt < 2; mt++)
        #pragma unroll
        for (int nt = 0; nt < 4; nt++) {
            const int col = nt * 8 + 2 * q;
            float bb0 = b1s[col], bb1 = b1s[col + 1];
            float c0 = C1[mt][nt][0] + bb0, c1 = C1[mt][nt][1] + bb1;
            float c2 = C1[mt][nt][2] + bb0, c3 = C1[mt][nt][3] + bb1;
            C1[mt][nt][0] = c0; C1[mt][nt][1] = c1;
            C1[mt][nt][2] = c2; C1[mt][nt][3] = c3;
            s[mt * 2 + 0] += c0 + c1;
            s[mt * 2 + 1] += c2 + c3;
            sq[mt * 2 + 0] = fmaf(c0, c0, fmaf(c1, c1, sq[mt * 2 + 0]));
            sq[mt * 2 + 1] = fmaf(c2, c2, fmaf(c3, c3, sq[mt * 2 + 1]));
        }
    float mu[4], rs[4];
    #pragma unroll
    for (int i = 0; i < 4; i++) {
        s[i]  += __shfl_xor_sync(0xffffffffu, s[i], 1);
        s[i]  += __shfl_xor_sync(0xffffffffu, s[i], 2);
        sq[i] += __shfl_xor_sync(0xffffffffu, sq[i], 1);
        sq[i] += __shfl_xor_sync(0xffffffffu, sq[i], 2);
        mu[i] = s[i] * (1.f / HH);
        rs[i] = rsqrtf(sq[i] * (1.f / HH) - mu[i] * mu[i] + 1e-5f) * 0.70710678118654752f;
    }

    // ================= LN affine + GELU (packed), keep as f32 pairs =================
    u64 Gp[2][4][2];    // [mt][nt][half: c01 / c23]
    #pragma unroll
    for (int nt = 0; nt < 4; nt++) {
        const int col = nt * 8 + 2 * q;
        u64 gp = *(const u64*)(gs + col);
        u64 bp = *(const u64*)(bls + col);
        #pragma unroll
        for (int mt = 0; mt < 2; mt++)
            #pragma unroll
            for (int h = 0; h < 2; h++) {
                const int row = mt * 2 + h;
                u64 c1p = mul2(dup2(rs[row]), gp);
                u64 c0p = fma2(dup2(-mu[row]), c1p, bp);
                u64 P = pk2(C1[mt][nt][2 * h], C1[mt][nt][2 * h + 1]);
                Gp[mt][nt][h] = gelu2p(fma2(P, c1p, c0p));
            }
    }

    // ================= A2 fragments from G (C-layout == A-layout chaining) =================
    uint32_t A2h[2][2][4], A2l[2][2][4];     // [mt][kchunk][reg]
    #pragma unroll
    for (int mt = 0; mt < 2; mt++)
        #pragma unroll
        for (int kc = 0; kc < 2; kc++) {
            split_pair(Gp[mt][kc * 2 + 0][0], A2h[mt][kc][0], A2l[mt][kc][0]);
            split_pair(Gp[mt][kc * 2 + 0][1], A2h[mt][kc][1], A2l[mt][kc][1]);
            split_pair(Gp[mt][kc * 2 + 1][0], A2h[mt][kc][2], A2l[mt][kc][2]);
            split_pair(Gp[mt][kc * 2 + 1][1], A2h[mt][kc][3], A2l[mt][kc][3]);
        }

    // ================= B2 fragments (w2: [H=32 K][F=16 N]) =================
    uint32_t B2h[2][2][2], B2l[2][2][2];     // [kchunk][nt][reg]
    {
        #pragma unroll
        for (int kc = 0; kc < 2; kc++)
            #pragma unroll
            for (int nt = 0; nt < 2; nt++) {
                const int n = nt * 8 + grp;
                const int k0 = kc * 16 + q * 2;
                float wa = __ldg(&w2[(k0    ) * FF + n]);
                float wb = __ldg(&w2[(k0 + 1) * FF + n]);
                float wc = __ldg(&w2[(k0 + 8) * FF + n]);
                float wd = __ldg(&w2[(k0 + 9) * FF + n]);
                uint32_t h0, l0, h1, l1;
                split_pair(pk2(wa, wb), h0, l0);
                split_pair(pk2(wc, wd), h1, l1);
                B2h[kc][nt][0] = h0; B2h[kc][nt][1] = h1;
                B2l[kc][nt][0] = l0; B2l[kc][nt][1] = l1;
            }
    }

    // ================= MMA2: y[2mt][2nt] = G x w2 (3-term split, K=32) =================
    float C2[2][2][4];
    #pragma unroll
    for (int mt = 0; mt < 2; mt++)
        #pragma unroll
        for (int nt = 0; nt < 2; nt++) {
            #pragma unroll
            for (int i = 0; i < 4; i++) C2[mt][nt][i] = 0.f;
            #pragma unroll
            for (int kc = 0; kc < 2; kc++) {
                mma16816(C2[mt][nt], A2h[mt][kc], B2h[kc][nt]);
                mma16816(C2[mt][nt], A2h[mt][kc], B2l[kc][nt]);
                mma16816(C2[mt][nt], A2l[mt][kc], B2h[kc][nt]);
            }
        }

    // ================= +b2, store (float2 per fragment half) =================
    const int W0 = R0 + rb;
    #pragma unroll
    for (int mt = 0; mt < 2; mt++)
        #pragma unroll
        for (int nt = 0; nt < 2; nt++) {
            const int row0 = W0 + mt * 16 + grp;
            const int col = nt * 8 + 2 * q;
            float b20 = b2s[col], b21 = b2s[col + 1];
            float2 v0 = make_float2(C2[mt][nt][0] + b20, C2[mt][nt][1] + b21);
            float2 v1 = make_float2(C2[mt][nt][2] + b20, C2[mt][nt][3] + b21);
            *(float2*)(out + (size_t)row0 * FF + col) = v0;
            *(float2*)(out + (size_t)(row0 + 8) * FF + col) = v1;
        }
}

extern "C" void kernel_launch(void* const* d_in, const int* in_sizes, int n_in,
                              void* d_out, int out_size) {
    const float* x          = (const float*)d_in[0];
    const int*   lab_idx    = (const int*)  d_in[1];
    const float* projection = (const float*)d_in[2];
    const float* bias       = (const float*)d_in[3];
    const float* w1         = (const float*)d_in[4];
    const float* b1         = (const float*)d_in[5];
    const float* ln_g       = (const float*)d_in[6];
    const float* ln_b       = (const float*)d_in[7];
    const float* w2         = (const float*)d_in[8];
    const float* b2         = (const float*)d_in[9];
    float* out = (float*)d_out;

    fused_mma_kernel<<<GRID_BLKS, THREADS>>>(
        x, lab_idx, projection, bias, w1, b1, ln_g, ln_b, w2, b2, out);
}